// round 10
// baseline (speedup 1.0000x reference)
#include <cuda_runtime.h>

#define DIM   64
#define TILE  128
#define NT    128
#define NSTEP 2
#define SKEW_CYC 1600

typedef unsigned long long u64;

// per-SM arrival tickets: consecutive CTAs on one SM get alternating parity.
// (static __device__ array — allowed; no dynamic allocation)
__device__ int g_ticket[1024];

// ---- packed f32x2 helpers (Blackwell FFMA2: 2x FFMA throughput) ----
__device__ __forceinline__ u64 fma2(u64 a, u64 b, u64 c){
    u64 d; asm("fma.rn.f32x2 %0, %1, %2, %3;" : "=l"(d) : "l"(a), "l"(b), "l"(c)); return d;
}
__device__ __forceinline__ u64 pack2(float lo, float hi){
    u64 r; asm("mov.b64 %0, {%1, %2};" : "=l"(r) : "f"(lo), "f"(hi)); return r;
}
__device__ __forceinline__ u64 dup2(float a){ return pack2(a, a); }
__device__ __forceinline__ float2 unpk(u64 v){
    float2 f; asm("mov.b64 {%0, %1}, %2;" : "=f"(f.x), "=f"(f.y) : "l"(v)); return f;
}

// smooth_leaky_relu: 0.1*x + 0.9*softplus(x), numerically stable
__device__ __forceinline__ float act(float x){
    float sp = fmaxf(x, 0.f) + __logf(1.f + __expf(-fabsf(x)));
    return fmaf(0.9f, sp, 0.1f * x);
}

// One CTA integrates a TILE x 64 slab through all NSTEP RK4 steps.
// Each thread owns 8 rows (stride-16 interleaved) x 8 cols (tx*4 / tx*4+32).
// Stage data is warp-private -> __syncwarp() only. ANTI-PHASE: the two CTAs
// co-resident on an SM are skewed by ~half a stage so one CTA's MUFU epilogue
// overlaps the other CTA's FFMA2 GEMM on each SMSP (symmetric contention
// otherwise phase-locks them, serializing the fma and MUFU pipes).
__global__ void __launch_bounds__(NT, 2) ode_rk4_kernel(
    const float* __restrict__ x, const float* __restrict__ W,
    const float* __restrict__ bias, float* __restrict__ out)
{
    extern __shared__ float smem[];
    float* sW  = smem;                 // [64][64] k-major: sW[k*64+c] = W[c][k+1]
    float* swt = sW + DIM * DIM;       // [64] t-coefficients W[c][0]
    float* sb  = swt + DIM;            // [64] bias
    float* sB0 = sb + DIM;             // [128][64] stage input (ping), swizzled
    float* sB1 = sB0 + TILE * DIM;     // [128][64] stage input (pong), swizzled
    __shared__ int s_par;

    const int tid = threadIdx.x;
    const int tx  = tid & 7;           // 8 col-groups
    const int ty  = tid >> 3;          // 16 row-groups; rows = ty + 16*j
    const int CA  = tx * 4;            // cols CA..CA+3
    const int CB  = CA + 32;           // cols CB..CB+3
    const int row0 = blockIdx.x * TILE;

    // arrival ticket -> skew parity (timing-only; output unaffected)
    if (tid == 0){
        unsigned smid; asm("mov.u32 %0, %%smid;" : "=r"(smid));
        s_par = atomicAdd(&g_ticket[smid & 1023], 1) & 1;
    }

    // swizzled chunk offsets (in floats) for this thread's two col-chunks
    const int chA = ((tx ^ ty) & 15) << 2;
    const int chB = (((tx + 8) ^ ty) & 15) << 2;

    int roff[8];                       // smem row bases (floats)
    #pragma unroll
    for (int j = 0; j < 8; j++) roff[j] = (ty + 16 * j) * DIM;

    // ---- load weights into smem (k-major; conflict-free LDS.128 on read) ----
    for (int i = tid; i < DIM * DIM; i += NT){
        int k = i >> 6, c = i & 63;
        sW[i] = W[c * (DIM + 1) + k + 1];
    }
    if (tid < DIM){ swt[tid] = W[tid * (DIM + 1)]; sb[tid] = bias[tid]; }
    __syncthreads();   // weights + s_par visible to all warps

    // ---- load y0, publish first stage input into sB0 (swizzled) ----
    float yv[8][8], av[8][8];
    #pragma unroll
    for (int j = 0; j < 8; j++){
        const float4* gx = reinterpret_cast<const float4*>(
            x + (size_t)(row0 + ty + 16 * j) * DIM);
        float4 vA = gx[tx];
        float4 vB = gx[tx + 8];
        yv[j][0]=vA.x; yv[j][1]=vA.y; yv[j][2]=vA.z; yv[j][3]=vA.w;
        yv[j][4]=vB.x; yv[j][5]=vB.y; yv[j][6]=vB.z; yv[j][7]=vB.w;
        *reinterpret_cast<float4*>(sB0 + roff[j] + chA) = vA;
        *reinterpret_cast<float4*>(sB0 + roff[j] + chB) = vB;
    }

    // ---- anti-phase skew: odd-ticket CTAs wait ~half a stage ----
    if (s_par){
        long long t0c = clock64();
        while (clock64() - t0c < SKEW_CYC) { }
    }

    const float h  = 1.0f / NSTEP;
    const float h2 = 0.5f * h;
    const float h6 = h * (1.0f / 6.0f);

    u64 pre[8][4];   // packed fp32 pairs: 8 rows x 4 col-pairs

// GEMM at time TT reading swizzled stage input from BUF:
// pre[j][p] = t*wt + b + sum_k BUF[r][k]*sW[k][c]
// __syncwarp suffices: this warp's stage rows are warp-private.
#define DO_GEMM(TT, BUF) { \
    __syncwarp(); \
    { \
        u64 t2  = dup2(TT); \
        u64 p0 = fma2(t2, *reinterpret_cast<const u64*>(swt + CA),     \
                          *reinterpret_cast<const u64*>(sb  + CA));    \
        u64 p1 = fma2(t2, *reinterpret_cast<const u64*>(swt + CA + 2), \
                          *reinterpret_cast<const u64*>(sb  + CA + 2));\
        u64 p2 = fma2(t2, *reinterpret_cast<const u64*>(swt + CB),     \
                          *reinterpret_cast<const u64*>(sb  + CB));    \
        u64 p3 = fma2(t2, *reinterpret_cast<const u64*>(swt + CB + 2), \
                          *reinterpret_cast<const u64*>(sb  + CB + 2));\
        _Pragma("unroll") \
        for (int j = 0; j < 8; j++){ \
            pre[j][0] = p0; pre[j][1] = p1; pre[j][2] = p2; pre[j][3] = p3; \
        } \
    } \
    _Pragma("unroll 4") \
    for (int k4 = 0; k4 < 16; k4++){ \
        float4 a4[8]; \
        const int swz = ((k4 ^ ty) & 15) << 2; \
        _Pragma("unroll") \
        for (int j = 0; j < 8; j++) \
            a4[j] = *reinterpret_cast<const float4*>((BUF) + roff[j] + swz); \
        _Pragma("unroll") \
        for (int kk = 0; kk < 4; kk++){ \
            const float* wrow = sW + (k4 * 4 + kk) * DIM; \
            ulonglong2 wA = *reinterpret_cast<const ulonglong2*>(wrow + CA); \
            ulonglong2 wB = *reinterpret_cast<const ulonglong2*>(wrow + CB); \
            _Pragma("unroll") \
            for (int j = 0; j < 8; j++){ \
                float  as = reinterpret_cast<const float*>(&a4[j])[kk]; \
                u64 a = dup2(as); \
                pre[j][0] = fma2(a, wA.x, pre[j][0]); \
                pre[j][1] = fma2(a, wA.y, pre[j][1]); \
                pre[j][2] = fma2(a, wB.x, pre[j][2]); \
                pre[j][3] = fma2(a, wB.y, pre[j][3]); \
            } \
        } \
    } \
    __syncwarp(); \
}

// unpack + activate one row's 8 pre-activations
#define ACT8(j, K) \
    float2 q0 = unpk(pre[j][0]), q1 = unpk(pre[j][1]); \
    float2 q2 = unpk(pre[j][2]), q3 = unpk(pre[j][3]); \
    float K[8] = { act(q0.x), act(q0.y), act(q1.x), act(q1.y), \
                   act(q2.x), act(q2.y), act(q3.x), act(q3.y) };

// epilogue: k = act(pre); acc-update; publish next stage input y + COEF*k
#define STAGE_EPI(WACC, COEF, FIRST, OUTB) { \
    _Pragma("unroll") \
    for (int j = 0; j < 8; j++){ \
        ACT8(j, kk) \
        _Pragma("unroll") \
        for (int i = 0; i < 8; i++){ \
            if (FIRST) av[j][i] = kk[i]; \
            else       av[j][i] = fmaf((WACC), kk[i], av[j][i]); \
        } \
        float4 wA4, wB4; \
        wA4.x = fmaf((COEF), kk[0], yv[j][0]); \
        wA4.y = fmaf((COEF), kk[1], yv[j][1]); \
        wA4.z = fmaf((COEF), kk[2], yv[j][2]); \
        wA4.w = fmaf((COEF), kk[3], yv[j][3]); \
        wB4.x = fmaf((COEF), kk[4], yv[j][4]); \
        wB4.y = fmaf((COEF), kk[5], yv[j][5]); \
        wB4.z = fmaf((COEF), kk[6], yv[j][6]); \
        wB4.w = fmaf((COEF), kk[7], yv[j][7]); \
        *reinterpret_cast<float4*>((OUTB) + roff[j] + chA) = wA4; \
        *reinterpret_cast<float4*>((OUTB) + roff[j] + chB) = wB4; \
    } \
}

// final stage: k4, y += h/6*(k1+2k2+2k3+k4), publish y for next step
#define STAGE_FIN(OUTB) { \
    _Pragma("unroll") \
    for (int j = 0; j < 8; j++){ \
        ACT8(j, kk) \
        _Pragma("unroll") \
        for (int i = 0; i < 8; i++){ \
            av[j][i] += kk[i]; \
            yv[j][i] = fmaf(h6, av[j][i], yv[j][i]); \
        } \
        float4 wA4, wB4; \
        wA4.x = yv[j][0]; wA4.y = yv[j][1]; wA4.z = yv[j][2]; wA4.w = yv[j][3]; \
        wB4.x = yv[j][4]; wB4.y = yv[j][5]; wB4.z = yv[j][6]; wB4.w = yv[j][7]; \
        *reinterpret_cast<float4*>((OUTB) + roff[j] + chA) = wA4; \
        *reinterpret_cast<float4*>((OUTB) + roff[j] + chB) = wB4; \
    } \
}

    #pragma unroll 1
    for (int s = 0; s < NSTEP; s++){
        float t0 = s * h;
        DO_GEMM(t0,      sB0);  STAGE_EPI(1.0f, h2, true,  sB1);   // k1
        DO_GEMM(t0 + h2, sB1);  STAGE_EPI(2.0f, h2, false, sB0);   // k2
        DO_GEMM(t0 + h2, sB0);  STAGE_EPI(2.0f, h,  false, sB1);   // k3
        DO_GEMM(t0 + h,  sB1);  STAGE_FIN(sB0);                    // k4
    }

    // ---- write result ----
    #pragma unroll
    for (int j = 0; j < 8; j++){
        float4* g = reinterpret_cast<float4*>(
            out + (size_t)(row0 + ty + 16 * j) * DIM);
        float4 vA, vB;
        vA.x=yv[j][0]; vA.y=yv[j][1]; vA.z=yv[j][2]; vA.w=yv[j][3];
        vB.x=yv[j][4]; vB.y=yv[j][5]; vB.z=yv[j][6]; vB.w=yv[j][7];
        g[tx]     = vA;
        g[tx + 8] = vB;
    }
}

extern "C" void kernel_launch(void* const* d_in, const int* in_sizes, int n_in,
                              void* d_out, int out_size)
{
    const float* x    = (const float*)d_in[0];
    const float* W    = (const float*)d_in[1];
    const float* bias = (const float*)d_in[2];
    float* out = (float*)d_out;

    int rows   = in_sizes[0] / DIM;     // 262144
    int blocks = rows / TILE;           // 2048

    size_t smem = (size_t)(DIM * DIM + 2 * DIM + 2 * TILE * DIM) * sizeof(float); // 82432 B
    cudaFuncSetAttribute(ode_rk4_kernel,
                         cudaFuncAttributeMaxDynamicSharedMemorySize, (int)smem);
    ode_rk4_kernel<<<blocks, NT, smem>>>(x, W, bias, out);
}

// round 14
// speedup vs baseline: 1.3984x; 1.3984x over previous
#include <cuda_runtime.h>
#include <cuda_bf16.h>
#include <stdint.h>

#define DIM   64
#define TILE  64      // rows per CTA = 4 warps x 16 rows
#define NT    128
#define NSTEP 2
#define KPAD  72      // Bt row stride in bf16 (conflict-free frag loads)

// pack two floats to bf16x2: e -> low half, o -> high half
static __device__ __forceinline__ uint32_t bf2(float e, float o){
    uint32_t r; asm("cvt.rn.bf16x2.f32 %0, %1, %2;" : "=r"(r) : "f"(o), "f"(e)); return r;
}
static __device__ __forceinline__ float lo_f(uint32_t p){ return __uint_as_float(p << 16); }
static __device__ __forceinline__ float hi_f(uint32_t p){ return __uint_as_float(p & 0xFFFF0000u); }

// smooth_leaky_relu: 0.1*x + 0.9*softplus(x)
static __device__ __forceinline__ float act(float x){
    float sp = fmaxf(x, 0.f) + __logf(1.f + __expf(-fabsf(x)));
    return fmaf(0.9f, sp, 0.1f * x);
}

#define MMA(d, a0, a1, a2, a3, b0v, b1v) \
    asm volatile("mma.sync.aligned.m16n8k16.row.col.f32.bf16.bf16.f32 " \
        "{%0,%1,%2,%3}, {%4,%5,%6,%7}, {%8,%9}, {%0,%1,%2,%3};" \
        : "+f"((d)[0]), "+f"((d)[1]), "+f"((d)[2]), "+f"((d)[3]) \
        : "r"(a0), "r"(a1), "r"(a2), "r"(a3), "r"(b0v), "r"(b1v))

// build A-fragments (hi+lo split) for n-tile j from 4 fp32 values.
// j even -> (a0,a1) of K-chunk j/2 ; j odd -> (a2,a3) of K-chunk j/2
#define PACKJ(j, z0, z1, z2, z3) { \
    uint32_t h0 = bf2(z0, z1), h1 = bf2(z2, z3); \
    ah[(j)>>1][2*((j)&1)]   = h0; \
    ah[(j)>>1][2*((j)&1)+1] = h1; \
    al[(j)>>1][2*((j)&1)]   = bf2((z0) - lo_f(h0), (z1) - hi_f(h0)); \
    al[(j)>>1][2*((j)&1)+1] = bf2((z2) - lo_f(h1), (z3) - hi_f(h1)); }

// D = Z @ Bt^T, 3-pass split: hi*hi + lo*hi + hi*lo (+ t/bias K-chunk 4)
#define GEMM() { \
    _Pragma("unroll") \
    for (int j = 0; j < 8; j++){ dv[j][0]=0.f; dv[j][1]=0.f; dv[j][2]=0.f; dv[j][3]=0.f; } \
    _Pragma("unroll") \
    for (int kc = 0; kc < 4; kc++){ \
        _Pragma("unroll") \
        for (int j = 0; j < 8; j++){ \
            const __nv_bfloat16* bp = BH + (8*j + g)*KPAD + 16*kc + 2*t4; \
            const __nv_bfloat16* lp = BL + (8*j + g)*KPAD + 16*kc + 2*t4; \
            uint32_t b0 = *(const uint32_t*)bp; \
            uint32_t b1 = *(const uint32_t*)(bp + 8); \
            uint32_t c0 = *(const uint32_t*)lp; \
            uint32_t c1 = *(const uint32_t*)(lp + 8); \
            MMA(dv[j], ah[kc][0], ah[kc][1], ah[kc][2], ah[kc][3], b0, b1); \
            MMA(dv[j], al[kc][0], al[kc][1], al[kc][2], al[kc][3], b0, b1); \
            MMA(dv[j], ah[kc][0], ah[kc][1], ah[kc][2], ah[kc][3], c0, c1); \
        } \
    } \
    _Pragma("unroll") \
    for (int j = 0; j < 8; j++){ \
        uint32_t b0 = *(const uint32_t*)(BH + (8*j + g)*KPAD + 64 + 2*t4); \
        uint32_t c0 = *(const uint32_t*)(BL + (8*j + g)*KPAD + 64 + 2*t4); \
        MMA(dv[j], ah4, ah4, 0u, 0u, b0, 0u); \
        MMA(dv[j], ah4, ah4, 0u, 0u, c0, 0u); \
    } }

// epilogue: k = act(D); RK accumulate; build next stage input fragments
#define EPI(WACC, FIRST, COEF, FIN, TNEXT, BUILD) { \
    _Pragma("unroll") \
    for (int j = 0; j < 8; j++){ \
        float k0 = act(dv[j][0]), k1 = act(dv[j][1]); \
        float k2 = act(dv[j][2]), k3 = act(dv[j][3]); \
        if (FIRST){ av[j][0]=k0; av[j][1]=k1; av[j][2]=k2; av[j][3]=k3; } \
        else { av[j][0] = fmaf((float)(WACC), k0, av[j][0]); \
               av[j][1] = fmaf((float)(WACC), k1, av[j][1]); \
               av[j][2] = fmaf((float)(WACC), k2, av[j][2]); \
               av[j][3] = fmaf((float)(WACC), k3, av[j][3]); } \
        float z0, z1, z2, z3; \
        if (FIN){ \
            yv[j][0] = fmaf(h6, av[j][0], yv[j][0]); z0 = yv[j][0]; \
            yv[j][1] = fmaf(h6, av[j][1], yv[j][1]); z1 = yv[j][1]; \
            yv[j][2] = fmaf(h6, av[j][2], yv[j][2]); z2 = yv[j][2]; \
            yv[j][3] = fmaf(h6, av[j][3], yv[j][3]); z3 = yv[j][3]; \
        } else { \
            z0 = fmaf((float)(COEF), k0, yv[j][0]); \
            z1 = fmaf((float)(COEF), k1, yv[j][1]); \
            z2 = fmaf((float)(COEF), k2, yv[j][2]); \
            z3 = fmaf((float)(COEF), k3, yv[j][3]); \
        } \
        if (BUILD){ PACKJ(j, z0, z1, z2, z3); } \
    } \
    if (BUILD){ ah4 = (t4 == 0) ? bf2((float)(TNEXT), 1.0f) : 0u; } }

__global__ void __launch_bounds__(NT) ode_mma(
    const float* __restrict__ x, const float* __restrict__ W,
    const float* __restrict__ bias, float* __restrict__ out)
{
    // Bt[n=out-col][k] bf16, hi & lo: k 0..63 = W[n][k+1], k64 = W[n][0], k65 = bias[n]
    __shared__ __align__(16) __nv_bfloat16 BH[64 * KPAD];
    __shared__ __align__(16) __nv_bfloat16 BL[64 * KPAD];

    const int tid  = threadIdx.x;
    const int lane = tid & 31;
    const int wid  = tid >> 5;
    const int g    = lane >> 2;       // mma group id (0..7)
    const int t4   = lane & 3;        // thread-in-group
    const int r0   = blockIdx.x * TILE + wid * 16 + g;   // rows r0, r0+8

    // zero Bt (padding cols 66..71 must be 0), then scatter W/bias hi/lo
    for (int i = tid; i < 64 * KPAD / 2; i += NT){
        reinterpret_cast<uint32_t*>(BH)[i] = 0;
        reinterpret_cast<uint32_t*>(BL)[i] = 0;
    }
    __syncthreads();
    for (int idx = tid; idx < 64 * 66; idx += NT){
        int c = idx / 66, q = idx - c * 66;
        float w; int col;
        if (q < 64){ col = q;  w = W[c * (DIM + 1) + q + 1]; }
        else if (q == 64){ col = 64; w = W[c * (DIM + 1)]; }
        else { col = 65; w = bias[c]; }
        __nv_bfloat16 hb = __float2bfloat16(w);
        BH[c * KPAD + col] = hb;
        BL[c * KPAD + col] = __float2bfloat16(w - __bfloat162float(hb));
    }
    __syncthreads();   // last barrier — warps run free from here

    float yv[8][4], av[8][4], dv[8][4];
    uint32_t ah[4][4], al[4][4], ah4;

    // load x into D-layout fragments (rows r0 / r0+8, cols 8j+2t4..+1)
    #pragma unroll
    for (int j = 0; j < 8; j++){
        float2 v0 = *reinterpret_cast<const float2*>(x + (size_t)r0 * DIM + 8*j + 2*t4);
        float2 v1 = *reinterpret_cast<const float2*>(x + (size_t)(r0 + 8) * DIM + 8*j + 2*t4);
        yv[j][0] = v0.x; yv[j][1] = v0.y; yv[j][2] = v1.x; yv[j][3] = v1.y;
    }
    #pragma unroll
    for (int j = 0; j < 8; j++){ PACKJ(j, yv[j][0], yv[j][1], yv[j][2], yv[j][3]); }
    ah4 = (t4 == 0) ? bf2(0.0f, 1.0f) : 0u;    // (t=0, 1) K-chunk

    const float hh = 1.0f / NSTEP;
    const float h2 = 0.5f * hh;
    const float h6 = hh * (1.0f / 6.0f);

    #pragma unroll 1
    for (int s = 0; s < NSTEP; s++){
        float t0 = s * hh;
        bool last = (s == NSTEP - 1);
        GEMM(); EPI(1.0f, 1, h2,  0, t0 + h2, 1);        // k1
        GEMM(); EPI(2.0f, 0, h2,  0, t0 + h2, 1);        // k2
        GEMM(); EPI(2.0f, 0, hh,  0, t0 + hh, 1);        // k3
        GEMM(); EPI(1.0f, 0, 0.f, 1, t0 + hh, !last);    // k4 + combine
    }

    #pragma unroll
    for (int j = 0; j < 8; j++){
        *reinterpret_cast<float2*>(out + (size_t)r0 * DIM + 8*j + 2*t4)
            = make_float2(yv[j][0], yv[j][1]);
        *reinterpret_cast<float2*>(out + (size_t)(r0 + 8) * DIM + 8*j + 2*t4)
            = make_float2(yv[j][2], yv[j][3]);
    }
}

extern "C" void kernel_launch(void* const* d_in, const int* in_sizes, int n_in,
                              void* d_out, int out_size)
{
    const float* x    = (const float*)d_in[0];
    const float* W    = (const float*)d_in[1];
    const float* bias = (const float*)d_in[2];
    float* out = (float*)d_out;

    int rows   = in_sizes[0] / DIM;     // 262144
    int blocks = rows / TILE;           // 4096

    ode_mma<<<blocks, NT>>>(x, W, bias, out);
}